// round 2
// baseline (speedup 1.0000x reference)
#include <cuda_runtime.h>
#include <cstdint>

typedef unsigned long long u64;
#define FULLMASK 0xffffffffu

// Static scratch (allocation-free rule): projected node features + softmax denom
__device__ float g_Q[100000 * 64];
__device__ float g_K[100000 * 64];
__device__ float g_V[100000 * 64];
__device__ float g_Z[100000 * 8];

// ---------------- packed f32x2 helpers (sm_100a) ----------------
__device__ __forceinline__ u64 ffma2(u64 a, u64 b, u64 c) {
    u64 d;
    asm("fma.rn.f32x2 %0, %1, %2, %3;" : "=l"(d) : "l"(a), "l"(b), "l"(c));
    return d;
}
__device__ __forceinline__ u64 pack2(float x, float y) {
    u64 r;
    asm("mov.b64 %0, {%1,%2};" : "=l"(r) : "f"(x), "f"(y));
    return r;
}
__device__ __forceinline__ float2 unpack2(u64 v) {
    float lo, hi;
    asm("mov.b64 {%0,%1}, %2;" : "=f"(lo), "=f"(hi) : "l"(v));
    return make_float2(lo, hi);
}
// 16B shared load straight into two b64 regs (no packing instructions)
__device__ __forceinline__ void lds_2xu64(u64& a, u64& b, uint32_t saddr) {
    asm volatile("ld.shared.v2.u64 {%0,%1}, [%2];" : "=l"(a), "=l"(b) : "r"(saddr));
}

// ---------------- kernel 0: zero output accumulator + Z ----------------
__global__ void ex_zero_kernel(float* __restrict__ out, int n) {
    int total = n * 64 + n * 8;
    for (int i = blockIdx.x * blockDim.x + threadIdx.x; i < total;
         i += gridDim.x * blockDim.x) {
        if (i < n * 64) out[i] = 0.0f;
        else            g_Z[i - n * 64] = 0.0f;
    }
}

// ---------------- kernel 1: Q/K/V projections ----------------
// One thread per node; x row in registers; all three weights transposed in SMEM
// (reads are warp-broadcast: every lane uses the same (w,j,c) address).
__global__ __launch_bounds__(256) void ex_proj_kernel(
    const float* __restrict__ x,
    const float* __restrict__ WQ, const float* __restrict__ WK,
    const float* __restrict__ WV, int n) {
    __shared__ float wst[3 * 64 * 64];  // exactly 48KB, transposed: wst[w][j][c]
    for (int idx = threadIdx.x; idx < 3 * 4096; idx += 256) {
        int wi = idx >> 12;
        int r = idx & 4095;           // r = c*64 + j (coalesced source read)
        int c = r >> 6, j = r & 63;
        const float* wsrc = (wi == 0) ? WQ : (wi == 1) ? WK : WV;
        wst[(wi << 12) + (j << 6) + c] = wsrc[r];
    }
    __syncthreads();

    int node = blockIdx.x * 256 + threadIdx.x;
    if (node >= n) return;

    float4 xv[16];
    const float4* xp = (const float4*)(x + (size_t)node * 64);
#pragma unroll
    for (int k = 0; k < 16; k++) xv[k] = xp[k];

#pragma unroll
    for (int wi = 0; wi < 3; wi++) {
        const float4* wp = (const float4*)(wst + (wi << 12));
        float* op = ((wi == 0) ? g_Q : (wi == 1) ? g_K : g_V) + (size_t)node * 64;
        for (int j = 0; j < 64; j++) {
            float a0 = 0.f, a1 = 0.f, a2 = 0.f, a3 = 0.f;
#pragma unroll
            for (int k = 0; k < 16; k++) {
                float4 w = wp[(j << 4) + k];  // broadcast across warp
                a0 = fmaf(xv[k].x, w.x, a0);
                a1 = fmaf(xv[k].y, w.y, a1);
                a2 = fmaf(xv[k].z, w.z, a2);
                a3 = fmaf(xv[k].w, w.w, a3);
            }
            op[j] = (a0 + a1) + (a2 + a3);
        }
    }
}

// ---------------- kernel 2: fused edge kernel ----------------
// Warp processes EB edges per batch. Lane owns head-dim pair (2*lane, 2*lane+1).
// Ef projection done with packed f32x2 FMA; WE^T and duplicated edge_attr staged
// in SMEM. Scatter via vector red.global.add.v4.f32.
constexpr int EB = 6;

__global__ __launch_bounds__(256) void ex_edge_kernel(
    const float* __restrict__ ea, const float* __restrict__ WE,
    const int* __restrict__ eidx, float* __restrict__ out, int ne) {
    // WEt[j2][c] = (WE[c][2*j2], WE[c][2*j2+1]); padded row (66) keeps LDS.128
    // phases conflict-free (lane stride 528B -> bank quad 4*lane mod 32).
    __shared__ float2 WEt[32][66];
    __shared__ float2 eadup[8][EB][64];  // eadup[w][i][c] = (ea[c], ea[c])

    for (int idx = threadIdx.x; idx < 4096; idx += 256) {
        int c = idx >> 6, j = idx & 63;
        float w = WE[idx];
        ((float*)&WEt[j >> 1][c])[j & 1] = w;
    }
    __syncthreads();

    const int* srcA = eidx;
    const int* dstA = eidx + ne;
    int warp = threadIdx.x >> 5, lane = threadIdx.x & 31;
    int gw = blockIdx.x * 8 + warp;
    int nw = gridDim.x * 8;

    uint32_t we_s = (uint32_t)__cvta_generic_to_shared(&WEt[lane][0]);
    uint32_t ea_s = (uint32_t)__cvta_generic_to_shared(&eadup[warp][0][0]);

    for (int base = gw * EB; base < ne; base += nw * EB) {
        int cnt = min(EB, ne - base);

        // stage duplicated edge_attr (streaming loads protect K/Q/V L2 residency)
#pragma unroll
        for (int i = 0; i < EB; i++) {
            if (i < cnt) {
                float2 a = __ldcs((const float2*)(ea + (size_t)(base + i) * 64) + lane);
                ((float4*)&eadup[warp][i][0])[lane] = make_float4(a.x, a.x, a.y, a.y);
            }
        }
        __syncwarp();

        u64 acc[EB];
#pragma unroll
        for (int i = 0; i < EB; i++) acc[i] = 0ull;  // bits(0,0)

        // Ef[e, hd] = sum_c ea[e,c] * WE[c,hd] for this lane's hd pair
#pragma unroll
        for (int c2 = 0; c2 < 32; c2++) {
            u64 wlo, whi;
            lds_2xu64(wlo, whi, we_s + c2 * 16);
#pragma unroll
            for (int i = 0; i < EB; i++) {
                u64 alo, ahi;
                lds_2xu64(alo, ahi, ea_s + i * 512 + c2 * 16);
                acc[i] = ffma2(alo, wlo, acc[i]);
                acc[i] = ffma2(ahi, whi, acc[i]);
            }
        }

        // epilogue per edge: gather K/Q/V, head-wise score, exp, scatter-add
#pragma unroll
        for (int i = 0; i < EB; i++) {
            if (i < cnt) {
                int e = base + i;
                int src = __ldg(srcA + e);
                int dst = __ldg(dstA + e);
                float2 k2 = ((const float2*)(g_K + (size_t)src * 64))[lane];
                float2 q2 = ((const float2*)(g_Q + (size_t)dst * 64))[lane];
                float2 v2 = ((const float2*)(g_V + (size_t)src * 64))[lane];
                float2 ef = unpack2(acc[i]);
                float part = k2.x * q2.x * ef.x + k2.y * q2.y * ef.y;
                // reduce over the 4 lanes of each head (lanes 4h..4h+3)
                part += __shfl_xor_sync(FULLMASK, part, 1);
                part += __shfl_xor_sync(FULLMASK, part, 2);
                float s = part * 0.35355339059327373f;  // 1/sqrt(8)
                s = fminf(5.0f, fmaxf(-5.0f, s));
                float sc = __expf(s);
                float mx = v2.x * sc, my = v2.y * sc;
                // pair lanes -> 16B vector reductions (half the red lane-ops)
                u64 nb = __shfl_down_sync(FULLMASK, pack2(mx, my), 1);
                if ((lane & 1) == 0) {
                    float2 n2 = unpack2(nb);
                    float* dp = out + (size_t)dst * 64 + 2 * lane;  // 16B aligned
                    asm volatile(
                        "red.global.add.v4.f32 [%0], {%1,%2,%3,%4};" ::"l"(dp),
                        "f"(mx), "f"(my), "f"(n2.x), "f"(n2.y)
                        : "memory");
                }
                if ((lane & 3) == 0) {
                    float* zp = g_Z + (size_t)dst * 8 + (lane >> 2);
                    asm volatile("red.global.add.f32 [%0], %1;" ::"l"(zp), "f"(sc)
                                 : "memory");
                }
            }
        }
        __syncwarp();
    }
}

// ---------------- kernel 3: normalize ----------------
__global__ void ex_final_kernel(float* __restrict__ out, int n) {
    int total = n * 64;
    for (int i = blockIdx.x * blockDim.x + threadIdx.x; i < total;
         i += gridDim.x * blockDim.x) {
        int node = i >> 6;
        int h = (i & 63) >> 3;
        out[i] = out[i] / (g_Z[node * 8 + h] + 1e-6f);
    }
}

extern "C" void kernel_launch(void* const* d_in, const int* in_sizes, int n_in,
                              void* d_out, int out_size) {
    const float* x  = (const float*)d_in[0];
    const float* ea = (const float*)d_in[1];
    const float* WQ = (const float*)d_in[2];
    const float* WK = (const float*)d_in[3];
    const float* WV = (const float*)d_in[4];
    const float* WE = (const float*)d_in[5];
    const int* eidx = (const int*)d_in[6];
    float* out = (float*)d_out;

    int n  = in_sizes[0] / 64;   // nodes
    int ne = in_sizes[6] / 2;    // edges

    ex_zero_kernel<<<2048, 256>>>(out, n);
    ex_proj_kernel<<<(n + 255) / 256, 256>>>(x, WQ, WK, WV, n);
    ex_edge_kernel<<<740, 256>>>(ea, WE, eidx, out, ne);
    ex_final_kernel<<<2048, 256>>>(out, n);
}

// round 3
// speedup vs baseline: 1.2104x; 1.2104x over previous
#include <cuda_runtime.h>
#include <cstdint>

typedef unsigned long long u64;
#define FULLMASK 0xffffffffu

// Static scratch (allocation-free rule): projected node features + softmax denom
__device__ float g_Q[100000 * 64];
__device__ float g_K[100000 * 64];
__device__ float g_V[100000 * 64];
__device__ float g_Z[100000 * 8];

// ---------------- packed f32x2 helpers (sm_100a) ----------------
__device__ __forceinline__ u64 ffma2(u64 a, u64 b, u64 c) {
    u64 d;
    asm("fma.rn.f32x2 %0, %1, %2, %3;" : "=l"(d) : "l"(a), "l"(b), "l"(c));
    return d;
}
__device__ __forceinline__ u64 pack2(float x, float y) {
    u64 r;
    asm("mov.b64 %0, {%1,%2};" : "=l"(r) : "f"(x), "f"(y));
    return r;
}
__device__ __forceinline__ float2 unpack2(u64 v) {
    float lo, hi;
    asm("mov.b64 {%0,%1}, %2;" : "=f"(lo), "=f"(hi) : "l"(v));
    return make_float2(lo, hi);
}
// 16B shared load straight into two b64 regs
__device__ __forceinline__ void lds_2xu64(u64& a, u64& b, uint32_t saddr) {
    asm volatile("ld.shared.v2.u64 {%0,%1}, [%2];" : "=l"(a), "=l"(b) : "r"(saddr));
}

// ---------------- kernel 0: zero output accumulator + Z ----------------
__global__ void ex_zero_kernel(float4* __restrict__ out, int n) {
    int total = n * 16 + n * 2;  // out as float4 + Z as float4
    float4 z4 = make_float4(0.f, 0.f, 0.f, 0.f);
    for (int i = blockIdx.x * blockDim.x + threadIdx.x; i < total;
         i += gridDim.x * blockDim.x) {
        if (i < n * 16) out[i] = z4;
        else            ((float4*)g_Z)[i - n * 16] = z4;
    }
}

// ---------------- kernel 1: Q/K/V projections (c-paired f32x2) ----------------
// Thread-per-node. Wt[m][j][c] = W_m[c][j] in smem (uniform-address broadcasts).
// acc_j = sum_c2 f32x2( (x[2c2],x[2c2+1]) * (W[2c2][j],W[2c2+1][j]) ), out = lo+hi.
__global__ __launch_bounds__(256) void ex_proj_kernel(
    const float* __restrict__ x,
    const float* __restrict__ WQ, const float* __restrict__ WK,
    const float* __restrict__ WV, int n) {
    __shared__ float Wt[3][64][64];  // 48KB, transposed per matrix
    for (int idx = threadIdx.x; idx < 3 * 4096; idx += 256) {
        int m = idx >> 12;
        int r = idx & 4095;          // r = c*64 + j (coalesced source read)
        int c = r >> 6, j = r & 63;
        const float* wsrc = (m == 0) ? WQ : (m == 1) ? WK : WV;
        Wt[m][j][c] = wsrc[r];
    }
    __syncthreads();

    int node = blockIdx.x * 256 + threadIdx.x;
    if (node >= n) return;

    // x row as natural u64 pairs (no pack movs)
    u64 xq[32];
    const ulonglong2* xp = (const ulonglong2*)(x + (size_t)node * 64);
#pragma unroll
    for (int k = 0; k < 16; k++) {
        ulonglong2 t = xp[k];
        xq[2 * k] = t.x;
        xq[2 * k + 1] = t.y;
    }

    uint32_t wt0 = (uint32_t)__cvta_generic_to_shared(&Wt[0][0][0]);

#pragma unroll 1
    for (int m = 0; m < 3; m++) {
        float* op = ((m == 0) ? g_Q : (m == 1) ? g_K : g_V) + (size_t)node * 64;
        uint32_t wtm = wt0 + m * 16384;
#pragma unroll 1
        for (int jg = 0; jg < 8; jg++) {       // 8 outputs per group
            uint32_t ga = wtm + jg * 2048;
            u64 acc[8];
#pragma unroll
            for (int jj = 0; jj < 8; jj++) acc[jj] = 0ull;
#pragma unroll
            for (int c4 = 0; c4 < 16; c4++) {
#pragma unroll
                for (int jj = 0; jj < 8; jj++) {
                    u64 w0, w1;
                    lds_2xu64(w0, w1, ga + jj * 256 + c4 * 16);
                    acc[jj] = ffma2(xq[2 * c4], w0, acc[jj]);
                    acc[jj] = ffma2(xq[2 * c4 + 1], w1, acc[jj]);
                }
            }
            float v[8];
#pragma unroll
            for (int jj = 0; jj < 8; jj++) {
                float2 e = unpack2(acc[jj]);
                v[jj] = e.x + e.y;
            }
            ((float4*)(op + jg * 8))[0] = make_float4(v[0], v[1], v[2], v[3]);
            ((float4*)(op + jg * 8))[1] = make_float4(v[4], v[5], v[6], v[7]);
        }
    }
}

// ---------------- kernel 2: fused edge kernel ----------------
// Warp batch of EB edges. Lane owns output dims (2l, 2l+1) via two c-paired
// f32x2 accumulators. WE held entirely in registers (64 u64/lane). edge_attr
// staged (non-duplicated) in double-buffered smem; broadcast LDS.128 feeds the
// natural multiplier pairs. K/Q/V gathers + next-batch loads issued before the
// GEMM loop to hide L2 latency.
constexpr int EB = 4;

__global__ __launch_bounds__(256, 1) void ex_edge_kernel(
    const float* __restrict__ ea, const float* __restrict__ WE,
    const int* __restrict__ eidx, float* __restrict__ out, int ne) {
    __shared__ float east[2][8][EB][64];  // 16KB double-buffered staging

    int warp = threadIdx.x >> 5, lane = threadIdx.x & 31;

    // WE columns (2l, 2l+1) as c-pairs in registers:
    // wA[c2] = (WE[2c2][2l],   WE[2c2+1][2l])
    // wB[c2] = (WE[2c2][2l+1], WE[2c2+1][2l+1])
    u64 wA[32], wB[32];
#pragma unroll
    for (int c2 = 0; c2 < 32; c2++) {
        float2 r0 = *(const float2*)(WE + (2 * c2) * 64 + 2 * lane);
        float2 r1 = *(const float2*)(WE + (2 * c2 + 1) * 64 + 2 * lane);
        wA[c2] = pack2(r0.x, r1.x);
        wB[c2] = pack2(r0.y, r1.y);
    }

    const int* srcA = eidx;
    const int* dstA = eidx + ne;
    int gw = blockIdx.x * 8 + warp;
    int nw = gridDim.x * 8;
    int stride = nw * EB;

    int base = gw * EB;
    if (base >= ne) return;

    // prolog: load first batch's indices + edge_attr
    float2 eaR[EB];
    int srcR[EB], dstR[EB];
#pragma unroll
    for (int i = 0; i < EB; i++) {
        int e = base + i;
        if (e < ne) {
            eaR[i] = __ldcs((const float2*)(ea + (size_t)e * 64) + lane);
            srcR[i] = __ldg(srcA + e);
            dstR[i] = __ldg(dstA + e);
        } else {
            eaR[i] = make_float2(0.f, 0.f);
            srcR[i] = 0; dstR[i] = 0;
        }
    }

    int par = 0;
    uint32_t sb0 = (uint32_t)__cvta_generic_to_shared(&east[0][warp][0][0]);

    while (base < ne) {
        // stage current batch (non-duplicated): lane writes its float2
#pragma unroll
        for (int i = 0; i < EB; i++)
            *(float2*)(&east[par][warp][i][2 * lane]) = eaR[i];
        __syncwarp();

        // issue K/Q/V gathers for current batch (latency hidden by GEMM)
        float2 k2[EB], q2[EB], v2[EB];
#pragma unroll
        for (int i = 0; i < EB; i++) {
            k2[i] = __ldg((const float2*)(g_K + (size_t)srcR[i] * 64) + lane);
            q2[i] = __ldg((const float2*)(g_Q + (size_t)dstR[i] * 64) + lane);
            v2[i] = __ldg((const float2*)(g_V + (size_t)srcR[i] * 64) + lane);
        }

        // prefetch next batch
        int nbase = base + stride;
        float2 eaN[EB];
        int srcN[EB], dstN[EB];
#pragma unroll
        for (int i = 0; i < EB; i++) {
            int e = nbase + i;
            if (e < ne) {
                eaN[i] = __ldcs((const float2*)(ea + (size_t)e * 64) + lane);
                srcN[i] = __ldg(srcA + e);
                dstN[i] = __ldg(dstA + e);
            } else {
                eaN[i] = make_float2(0.f, 0.f);
                srcN[i] = 0; dstN[i] = 0;
            }
        }

        // GEMM: Ef[e][2l], Ef[e][2l+1] via c-paired f32x2
        u64 accA[EB], accB[EB];
#pragma unroll
        for (int i = 0; i < EB; i++) { accA[i] = 0ull; accB[i] = 0ull; }
        uint32_t sb = sb0 + par * 8192;
#pragma unroll
        for (int c4 = 0; c4 < 16; c4++) {
#pragma unroll
            for (int i = 0; i < EB; i++) {
                u64 m0, m1;  // (ea[4c4],ea[4c4+1]), (ea[4c4+2],ea[4c4+3]) broadcast
                lds_2xu64(m0, m1, sb + i * 256 + c4 * 16);
                accA[i] = ffma2(m0, wA[2 * c4], accA[i]);
                accA[i] = ffma2(m1, wA[2 * c4 + 1], accA[i]);
                accB[i] = ffma2(m0, wB[2 * c4], accB[i]);
                accB[i] = ffma2(m1, wB[2 * c4 + 1], accB[i]);
            }
        }

        // epilogue
#pragma unroll
        for (int i = 0; i < EB; i++) {
            if (base + i < ne) {
                float2 ua = unpack2(accA[i]);
                float2 ub = unpack2(accB[i]);
                float efx = ua.x + ua.y;
                float efy = ub.x + ub.y;
                float part = k2[i].x * q2[i].x * efx + k2[i].y * q2[i].y * efy;
                part += __shfl_xor_sync(FULLMASK, part, 1);
                part += __shfl_xor_sync(FULLMASK, part, 2);
                float s = part * 0.35355339059327373f;  // 1/sqrt(8)
                s = fminf(5.0f, fmaxf(-5.0f, s));
                float sc = __expf(s);
                float mx = v2[i].x * sc, my = v2[i].y * sc;
                u64 nb = __shfl_down_sync(FULLMASK, pack2(mx, my), 1);
                int dst = dstR[i];
                if ((lane & 1) == 0) {
                    float2 n2 = unpack2(nb);
                    float* dp = out + (size_t)dst * 64 + 2 * lane;  // 16B aligned
                    asm volatile(
                        "red.global.add.v4.f32 [%0], {%1,%2,%3,%4};" ::"l"(dp),
                        "f"(mx), "f"(my), "f"(n2.x), "f"(n2.y)
                        : "memory");
                }
                if ((lane & 3) == 0) {
                    float* zp = g_Z + (size_t)dst * 8 + (lane >> 2);
                    asm volatile("red.global.add.f32 [%0], %1;" ::"l"(zp), "f"(sc)
                                 : "memory");
                }
            }
        }

        // rotate pipeline
#pragma unroll
        for (int i = 0; i < EB; i++) {
            eaR[i] = eaN[i]; srcR[i] = srcN[i]; dstR[i] = dstN[i];
        }
        base = nbase;
        par ^= 1;
    }
}

// ---------------- kernel 3: normalize (float4) ----------------
__global__ void ex_final_kernel(float4* __restrict__ out, int n) {
    int total = n * 16;
    for (int i = blockIdx.x * blockDim.x + threadIdx.x; i < total;
         i += gridDim.x * blockDim.x) {
        int node = i >> 4;
        int h = (i & 15) >> 1;  // 2 float4 per head
        float inv = __frcp_rn(g_Z[node * 8 + h] + 1e-6f);
        float4 v = out[i];
        v.x *= inv; v.y *= inv; v.z *= inv; v.w *= inv;
        out[i] = v;
    }
}

extern "C" void kernel_launch(void* const* d_in, const int* in_sizes, int n_in,
                              void* d_out, int out_size) {
    const float* x  = (const float*)d_in[0];
    const float* ea = (const float*)d_in[1];
    const float* WQ = (const float*)d_in[2];
    const float* WK = (const float*)d_in[3];
    const float* WV = (const float*)d_in[4];
    const float* WE = (const float*)d_in[5];
    const int* eidx = (const int*)d_in[6];
    float* out = (float*)d_out;

    int n  = in_sizes[0] / 64;   // nodes
    int ne = in_sizes[6] / 2;    // edges

    ex_zero_kernel<<<1024, 256>>>((float4*)out, n);
    ex_proj_kernel<<<(n + 255) / 256, 256>>>(x, WQ, WK, WV, n);
    ex_edge_kernel<<<296, 256>>>(ea, WE, eidx, out, ne);
    ex_final_kernel<<<1024, 256>>>((float4*)out, n);
}